// round 8
// baseline (speedup 1.0000x reference)
#include <cuda_runtime.h>
#include <cstdint>

#define D      768
#define LSEQ   528
#define BSZ    64
#define NHEADS 12
#define DH     64
#define MTOT   (BSZ * LSEQ)           // 33792
#define SCALE  0.03608439182435161f   // 768^-0.5
#define WELEM  (D * D)                // 589824

// Scratch (allocation-free rule: __device__ globals). All tf32-as-uint32.
__device__ uint32_t g_xt[(size_t)MTOT * D];
__device__ uint32_t g_qt[(size_t)MTOT * D];
__device__ uint32_t g_kt[(size_t)MTOT * D];
__device__ uint32_t g_vt[(size_t)MTOT * D];
__device__ uint32_t g_att[(size_t)MTOT * D];
__device__ uint32_t g_wt[4 * (size_t)WELEM];   // Wq, Wk, Wv, Wp (tf32)

__device__ __forceinline__ uint32_t f2tf32(float f) {
    uint32_t u;
    asm("cvt.rna.tf32.f32 %0, %1;" : "=r"(u) : "f"(f));
    return u;
}

__device__ __forceinline__ void mma_tf32(float c[4], uint32_t a0, uint32_t a1,
                                         uint32_t a2, uint32_t a3,
                                         uint32_t b0, uint32_t b1) {
    asm volatile(
        "mma.sync.aligned.m16n8k8.row.col.f32.tf32.tf32.f32 "
        "{%0,%1,%2,%3}, {%4,%5,%6,%7}, {%8,%9}, {%0,%1,%2,%3};"
        : "+f"(c[0]), "+f"(c[1]), "+f"(c[2]), "+f"(c[3])
        : "r"(a0), "r"(a1), "r"(a2), "r"(a3), "r"(b0), "r"(b1));
}

__device__ __forceinline__ void cp16(uint32_t smem_dst, const void* gsrc) {
    asm volatile("cp.async.cg.shared.global [%0], [%1], 16;\n"
                 :: "r"(smem_dst), "l"(gsrc));
}
#define CP_COMMIT() asm volatile("cp.async.commit_group;\n" ::: "memory")
#define CP_WAIT(N)  asm volatile("cp.async.wait_group %0;\n" :: "n"(N) : "memory")

// ---------------------------------------------------------------------------
// Single fused fp32 -> tf32 convert: x followed by the 4 weights.
// ---------------------------------------------------------------------------
#define XN4 ((MTOT * (size_t)D) / 4)     // 6488064
#define WN4 (WELEM / 4)                  // 147456
#define TOTN4 (XN4 + 4 * (size_t)WN4)    // 7077888

__global__ void cvt_all_kernel(const float* __restrict__ x,
                               const float* __restrict__ Wq,
                               const float* __restrict__ Wk,
                               const float* __restrict__ Wv,
                               const float* __restrict__ Wp,
                               uint32_t* __restrict__ xt,
                               uint32_t* __restrict__ wt)
{
    size_t i = (size_t)blockIdx.x * blockDim.x + threadIdx.x;
    if (i >= TOTN4) return;
    const float* src;
    uint32_t* dst;
    if (i < XN4) {
        src = x + 4 * i;
        dst = xt + 4 * i;
    } else {
        size_t wi = i - XN4;
        int w = (int)(wi / WN4);
        size_t off = (wi % WN4) * 4;
        const float* ws[4] = {Wq, Wk, Wv, Wp};
        src = ws[w] + off;
        dst = wt + (size_t)w * WELEM + off;
    }
    float4 v = *(const float4*)src;
    *(uint4*)dst = make_uint4(f2tf32(v.x), f2tf32(v.y), f2tf32(v.z), f2tf32(v.w));
}

// ---------------------------------------------------------------------------
// tf32 tensor-core GEMM: C[M,768] = A[M,768] @ W[768,768]
// 128x128 CTA tile, BK=16, 256 threads (8 warps 2x4), warp tile 64x32.
// acc = 64 regs/thread -> 2 CTAs/SM (16 warps, 4/SMSP).
// 3-stage cp.async pipeline, one __syncthreads per K-iter.
// ---------------------------------------------------------------------------
#define BM 128
#define BN 128
#define BK 16
#define NT (D / BK)      // 48
#define ASTR 20
#define BSTR 132
#define A_WORDS (BM * ASTR)               // 2560
#define STAGE_WORDS (A_WORDS + BK * BSTR) // 2560 + 2112 = 4672

template <int OUTMODE>
__device__ __forceinline__ void gemm_body(const uint32_t* __restrict__ A,
                                          const uint32_t* __restrict__ W,
                                          void* __restrict__ Cout,
                                          const float* __restrict__ bias)
{
    __shared__ uint32_t smem[3 * STAGE_WORDS];

    const int tid = threadIdx.x;
    const int lane = tid & 31;
    const int warp = tid >> 5;          // 0..7
    const int g  = lane >> 2;
    const int tg = lane & 3;
    const int mb = (warp >> 2) * 64;    // 2 warp-rows
    const int nb = (warp & 3) * 32;     // 4 warp-cols
    const int m0 = blockIdx.y * BM;
    const int n0 = blockIdx.x * BN;

    const uint32_t smBase = (uint32_t)__cvta_generic_to_shared(smem);

    auto load_tiles = [&](int kt, int buf) {
        const uint32_t aS = smBase + (uint32_t)(buf * STAGE_WORDS) * 4;
        const uint32_t bS = aS + A_WORDS * 4;
#pragma unroll
        for (int i = 0; i < 2; ++i) {
            int c = tid + (i << 8);
            int row = c >> 2;
            int co = (c & 3) << 2;
            cp16(aS + (uint32_t)(row * ASTR + co) * 4,
                 A + (size_t)(m0 + row) * D + kt * BK + co);
        }
#pragma unroll
        for (int i = 0; i < 2; ++i) {
            int c = tid + (i << 8);
            int row = c >> 5;
            int col = (c & 31) << 2;
            cp16(bS + (uint32_t)(row * BSTR + col) * 4,
                 W + (size_t)(kt * BK + row) * D + n0 + col);
        }
    };

    float acc[4][4][4] = {};

    load_tiles(0, 0); CP_COMMIT();
    load_tiles(1, 1); CP_COMMIT();

    for (int kt = 0; kt < NT; ++kt) {
        const int buf = kt % 3;
        if (kt + 1 < NT) { CP_WAIT(1); } else { CP_WAIT(0); }
        __syncthreads();
        if (kt + 2 < NT) {
            load_tiles(kt + 2, (kt + 2) % 3);
            CP_COMMIT();
        }

        const uint32_t* as = smem + buf * STAGE_WORDS;
        const uint32_t* bs = as + A_WORDS;
#pragma unroll
        for (int kk = 0; kk < BK; kk += 8) {
            uint32_t af[4][4];
#pragma unroll
            for (int i = 0; i < 4; ++i) {
                const int r = (mb + i * 16 + g) * ASTR + kk + tg;
                af[i][0] = as[r];
                af[i][1] = as[r + 8 * ASTR];
                af[i][2] = as[r + 4];
                af[i][3] = as[r + 8 * ASTR + 4];
            }
#pragma unroll
            for (int j = 0; j < 4; ++j) {
                const uint32_t b0 = bs[(kk + tg) * BSTR + nb + j * 8 + g];
                const uint32_t b1 = bs[(kk + tg + 4) * BSTR + nb + j * 8 + g];
#pragma unroll
                for (int i = 0; i < 4; ++i)
                    mma_tf32(acc[i][j], af[i][0], af[i][1], af[i][2], af[i][3], b0, b1);
            }
        }
    }

    // Epilogue (validated c-frag map)
#pragma unroll
    for (int j = 0; j < 4; ++j) {
        const int cn = n0 + nb + j * 8 + 2 * tg;
        float b0 = 0.f, b1 = 0.f;
        if (OUTMODE == 1) { b0 = bias[cn]; b1 = bias[cn + 1]; }
#pragma unroll
        for (int i = 0; i < 4; ++i) {
            const int rm = m0 + mb + i * 16 + g;
            if (OUTMODE == 0) {
                uint32_t* C = (uint32_t*)Cout;
                *(uint2*)(C + (size_t)rm * D + cn) =
                    make_uint2(f2tf32(acc[i][j][0]), f2tf32(acc[i][j][1]));
                *(uint2*)(C + (size_t)(rm + 8) * D + cn) =
                    make_uint2(f2tf32(acc[i][j][2]), f2tf32(acc[i][j][3]));
            } else {
                float* C = (float*)Cout;
                *(float2*)(C + (size_t)rm * D + cn) =
                    make_float2(acc[i][j][0] + b0, acc[i][j][1] + b1);
                *(float2*)(C + (size_t)(rm + 8) * D + cn) =
                    make_float2(acc[i][j][2] + b0, acc[i][j][3] + b1);
            }
        }
    }
}

__global__ void __launch_bounds__(256, 2) qkv_kernel()
{
    const uint32_t* W = g_wt + (size_t)blockIdx.z * WELEM;
    uint32_t* C = (blockIdx.z == 0) ? g_qt : (blockIdx.z == 1) ? g_kt : g_vt;
    gemm_body<0>(g_xt, W, C, nullptr);
}

__global__ void __launch_bounds__(256, 2) proj_kernel(const float* __restrict__ bias,
                                                      float* __restrict__ out)
{
    gemm_body<1>(g_att, g_wt + 3 * (size_t)WELEM, out, bias);
}

// ---------------------------------------------------------------------------
// tf32 flash attention, 128-query tile, 256 threads (8 warps x 16 rows).
// Separate P buffer -> no block syncs between S, softmax, PV (only syncwarp).
// q-tile 0 = queries [0,128) (nk=128); tiles 1..4 = [128,528) (nk=528).
// ---------------------------------------------------------------------------
#define QSTR 132
#define KSTR 68
#define PSTR 68
#define SM_QT 0
#define SM_KS (64 * QSTR)
#define SM_VS (SM_KS + 64 * KSTR)
#define SM_PS (SM_VS + 64 * KSTR)
#define SMEM_ATTN ((SM_PS + 128 * PSTR) * 4)   // 103424 B

__global__ void __launch_bounds__(256) attn_kernel()
{
    extern __shared__ uint32_t sm[];
    uint32_t* Qt = sm + SM_QT;   // [d][q]   64 x 128, stride 132
    uint32_t* Ks = sm + SM_KS;   // [d][key] 64 x 64,  stride 68
    uint32_t* Vs = sm + SM_VS;   // [key][d] 64 x 64,  stride 68
    uint32_t* Ps = sm + SM_PS;   // [q][key] 128 x 64, stride 68

    const int h = blockIdx.y, b = blockIdx.z;
    const int q0 = blockIdx.x << 7;
    const int nq = min(128, LSEQ - q0);
    const int nk = (q0 == 0) ? 128 : LSEQ;
    const int tid = threadIdx.x;
    const int lane = tid & 31;
    const int warp = tid >> 5;      // 0..7
    const int g  = lane >> 2;
    const int tg = lane & 3;
    const int mrow = warp * 16;
    const size_t base = (size_t)b * LSEQ * D + (size_t)h * DH;

    // Load Q transposed: Qt[d][q]
#pragma unroll
    for (int it = 0; it < 8; ++it) {
        int idx = tid + (it << 8);
        int r = idx & 127;
        int c4 = (idx >> 7) << 2;
        uint4 v = make_uint4(0u, 0u, 0u, 0u);
        if (r < nq) v = *(const uint4*)(g_qt + base + (size_t)(q0 + r) * D + c4);
        Qt[(c4 + 0) * QSTR + r] = v.x;
        Qt[(c4 + 1) * QSTR + r] = v.y;
        Qt[(c4 + 2) * QSTR + r] = v.z;
        Qt[(c4 + 3) * QSTR + r] = v.w;
    }

    float o[8][4] = {};
    float row_max[2] = {-1e30f, -1e30f};
    float row_sum[2] = {0.f, 0.f};

    for (int kt0 = 0; kt0 < nk; kt0 += 64) {
        const int nkv = min(64, nk - kt0);
        __syncthreads();   // prev-iter PV reads of Vs done (and Qt stores, iter 0)

        // Load K transposed + V row-major (zero-padded)
#pragma unroll
        for (int it = 0; it < 4; ++it) {
            int idx = tid + (it << 8);
            int r = idx & 63;
            int c4 = (idx >> 6) << 2;
            uint4 kv = make_uint4(0u, 0u, 0u, 0u);
            if (r < nkv) kv = *(const uint4*)(g_kt + base + (size_t)(kt0 + r) * D + c4);
            Ks[(c4 + 0) * KSTR + r] = kv.x;
            Ks[(c4 + 1) * KSTR + r] = kv.y;
            Ks[(c4 + 2) * KSTR + r] = kv.z;
            Ks[(c4 + 3) * KSTR + r] = kv.w;
            int r2 = idx >> 4;
            int c2 = (idx & 15) << 2;
            uint4 vv = make_uint4(0u, 0u, 0u, 0u);
            if (r2 < nkv) vv = *(const uint4*)(g_vt + base + (size_t)(kt0 + r2) * D + c2);
            *(uint4*)&Vs[r2 * KSTR + c2] = vv;
        }
        __syncthreads();

        // S = Q K^T : warp rows [mrow, mrow+16) x 64 keys
        float s[8][4] = {};
#pragma unroll
        for (int kk = 0; kk < 64; kk += 8) {
            uint32_t a0 = Qt[(kk + tg) * QSTR + mrow + g];
            uint32_t a1 = Qt[(kk + tg) * QSTR + mrow + g + 8];
            uint32_t a2 = Qt[(kk + tg + 4) * QSTR + mrow + g];
            uint32_t a3 = Qt[(kk + tg + 4) * QSTR + mrow + g + 8];
#pragma unroll
            for (int j = 0; j < 8; ++j) {
                uint32_t b0 = Ks[(kk + tg) * KSTR + j * 8 + g];
                uint32_t b1 = Ks[(kk + tg + 4) * KSTR + j * 8 + g];
                mma_tf32(s[j], a0, a1, a2, a3, b0, b1);
            }
        }

        // scale + mask
#pragma unroll
        for (int j = 0; j < 8; ++j) {
            const int col = kt0 + j * 8 + 2 * tg;
#pragma unroll
            for (int c = 0; c < 4; ++c) {
                float sv = s[j][c] * SCALE;
                if (col + (c & 1) >= nk) sv = -1e30f;
                s[j][c] = sv;
            }
        }

        // warp-local online softmax
        float m0v = -1e30f, m1v = -1e30f;
#pragma unroll
        for (int j = 0; j < 8; ++j) {
            m0v = fmaxf(m0v, fmaxf(s[j][0], s[j][1]));
            m1v = fmaxf(m1v, fmaxf(s[j][2], s[j][3]));
        }
        m0v = fmaxf(m0v, __shfl_xor_sync(0xffffffffu, m0v, 1));
        m0v = fmaxf(m0v, __shfl_xor_sync(0xffffffffu, m0v, 2));
        m1v = fmaxf(m1v, __shfl_xor_sync(0xffffffffu, m1v, 1));
        m1v = fmaxf(m1v, __shfl_xor_sync(0xffffffffu, m1v, 2));

        float nm0 = fmaxf(row_max[0], m0v);
        float nm1 = fmaxf(row_max[1], m1v);
        float corr0 = __expf(row_max[0] - nm0);
        float corr1 = __expf(row_max[1] - nm1);
        row_max[0] = nm0; row_max[1] = nm1;
        row_sum[0] *= corr0; row_sum[1] *= corr1;
#pragma unroll
        for (int j = 0; j < 8; ++j) {
            o[j][0] *= corr0; o[j][1] *= corr0;
            o[j][2] *= corr1; o[j][3] *= corr1;
        }

        float ps0 = 0.f, ps1 = 0.f;
#pragma unroll
        for (int j = 0; j < 8; ++j) {
            const int col = j * 8 + 2 * tg;
            float p0 = __expf(s[j][0] - nm0);
            float p1 = __expf(s[j][1] - nm0);
            float p2 = __expf(s[j][2] - nm1);
            float p3 = __expf(s[j][3] - nm1);
            ps0 += p0 + p1; ps1 += p2 + p3;
            Ps[(mrow + g) * PSTR + col]         = f2tf32(p0);
            Ps[(mrow + g) * PSTR + col + 1]     = f2tf32(p1);
            Ps[(mrow + g + 8) * PSTR + col]     = f2tf32(p2);
            Ps[(mrow + g + 8) * PSTR + col + 1] = f2tf32(p3);
        }
        ps0 += __shfl_xor_sync(0xffffffffu, ps0, 1);
        ps0 += __shfl_xor_sync(0xffffffffu, ps0, 2);
        ps1 += __shfl_xor_sync(0xffffffffu, ps1, 1);
        ps1 += __shfl_xor_sync(0xffffffffu, ps1, 2);
        row_sum[0] += ps0; row_sum[1] += ps1;
        __syncwarp();   // this warp's P rows fully visible to this warp

        // O += P @ V (warp reads only its own P rows)
#pragma unroll
        for (int kk = 0; kk < 64; kk += 8) {
            uint32_t a0 = Ps[(mrow + g) * PSTR + kk + tg];
            uint32_t a1 = Ps[(mrow + g + 8) * PSTR + kk + tg];
            uint32_t a2 = Ps[(mrow + g) * PSTR + kk + tg + 4];
            uint32_t a3 = Ps[(mrow + g + 8) * PSTR + kk + tg + 4];
#pragma unroll
            for (int j = 0; j < 8; ++j) {
                uint32_t b0 = Vs[(kk + tg) * KSTR + j * 8 + g];
                uint32_t b1 = Vs[(kk + tg + 4) * KSTR + j * 8 + g];
                mma_tf32(o[j], a0, a1, a2, a3, b0, b1);
            }
        }
    }

    const int r0 = mrow + g, r1 = r0 + 8;
    const float inv0 = 1.f / row_sum[0];
    const float inv1 = 1.f / row_sum[1];
#pragma unroll
    for (int j = 0; j < 8; ++j) {
        const int cn = j * 8 + 2 * tg;
        if (r0 < nq)
            *(uint2*)(g_att + base + (size_t)(q0 + r0) * D + cn) =
                make_uint2(f2tf32(o[j][0] * inv0), f2tf32(o[j][1] * inv0));
        if (r1 < nq)
            *(uint2*)(g_att + base + (size_t)(q0 + r1) * D + cn) =
                make_uint2(f2tf32(o[j][2] * inv1), f2tf32(o[j][3] * inv1));
    }
}

// ---------------------------------------------------------------------------
extern "C" void kernel_launch(void* const* d_in, const int* in_sizes, int n_in,
                              void* d_out, int out_size)
{
    const float* x   = (const float*)d_in[0];
    const float* Wq  = (const float*)d_in[1];
    const float* Wk  = (const float*)d_in[2];
    const float* Wv  = (const float*)d_in[3];
    const float* Wp  = (const float*)d_in[4];
    const float* bp  = (const float*)d_in[5];
    float* out = (float*)d_out;

    cudaFuncSetAttribute(attn_kernel,
                         cudaFuncAttributeMaxDynamicSharedMemorySize, SMEM_ATTN);

    uint32_t* g_xt_p;  cudaGetSymbolAddress((void**)&g_xt_p, g_xt);
    uint32_t* g_wt_p;  cudaGetSymbolAddress((void**)&g_wt_p, g_wt);

    const int cvt_blocks = (int)((TOTN4 + 255) / 256);
    cvt_all_kernel<<<cvt_blocks, 256>>>(x, Wq, Wk, Wv, Wp, g_xt_p, g_wt_p);

    dim3 gq(D / BN, MTOT / BM, 3);           // (6, 264, 3)
    qkv_kernel<<<gq, 256>>>();

    dim3 ga((LSEQ + 127) / 128, NHEADS, BSZ); // (5, 12, 64)
    attn_kernel<<<ga, 256, SMEM_ATTN>>>();

    dim3 gp(D / BN, MTOT / BM, 1);           // (6, 264)
    proj_kernel<<<gp, 256>>>(bp, out);
}

// round 11
// speedup vs baseline: 1.1495x; 1.1495x over previous
#include <cuda_runtime.h>
#include <cstdint>

#define D      768
#define LSEQ   528
#define BSZ    64
#define NHEADS 12
#define DH     64
#define MTOT   (BSZ * LSEQ)           // 33792
#define SCALE2 0.052058773f           // 768^-0.5 * log2(e)
#define WELEM  (D * D)                // 589824

// Scratch (allocation-free rule: __device__ globals). All tf32-as-uint32.
__device__ uint32_t g_xt[(size_t)MTOT * D];
__device__ uint32_t g_qt[(size_t)MTOT * D];
__device__ uint32_t g_kt[(size_t)MTOT * D];
__device__ uint32_t g_vt[(size_t)MTOT * D];
__device__ uint32_t g_att[(size_t)MTOT * D];
__device__ uint32_t g_wt[4 * (size_t)WELEM];   // Wq, Wk, Wv, Wp (tf32)

__device__ __forceinline__ uint32_t f2tf32(float f) {
    uint32_t u;
    asm("cvt.rna.tf32.f32 %0, %1;" : "=r"(u) : "f"(f));
    return u;
}

__device__ __forceinline__ float ex2f(float x) {
    float y;
    asm("ex2.approx.f32 %0, %1;" : "=f"(y) : "f"(x));
    return y;
}

__device__ __forceinline__ void mma_tf32(float c[4], uint32_t a0, uint32_t a1,
                                         uint32_t a2, uint32_t a3,
                                         uint32_t b0, uint32_t b1) {
    asm volatile(
        "mma.sync.aligned.m16n8k8.row.col.f32.tf32.tf32.f32 "
        "{%0,%1,%2,%3}, {%4,%5,%6,%7}, {%8,%9}, {%0,%1,%2,%3};"
        : "+f"(c[0]), "+f"(c[1]), "+f"(c[2]), "+f"(c[3])
        : "r"(a0), "r"(a1), "r"(a2), "r"(a3), "r"(b0), "r"(b1));
}

__device__ __forceinline__ void cp16(uint32_t smem_dst, const void* gsrc) {
    asm volatile("cp.async.cg.shared.global [%0], [%1], 16;\n"
                 :: "r"(smem_dst), "l"(gsrc));
}
#define CP_COMMIT() asm volatile("cp.async.commit_group;\n" ::: "memory")
#define CP_WAIT(N)  asm volatile("cp.async.wait_group %0;\n" :: "n"(N) : "memory")

// ---------------------------------------------------------------------------
// Single fused fp32 -> tf32 convert: x followed by the 4 weights.
// ---------------------------------------------------------------------------
#define XN4 ((MTOT * (size_t)D) / 4)     // 6488064
#define WN4 (WELEM / 4)                  // 147456
#define TOTN4 (XN4 + 4 * (size_t)WN4)    // 7077888

__global__ void cvt_all_kernel(const float* __restrict__ x,
                               const float* __restrict__ Wq,
                               const float* __restrict__ Wk,
                               const float* __restrict__ Wv,
                               const float* __restrict__ Wp,
                               uint32_t* __restrict__ xt,
                               uint32_t* __restrict__ wt)
{
    size_t i = (size_t)blockIdx.x * blockDim.x + threadIdx.x;
    if (i >= TOTN4) return;
    const float* src;
    uint32_t* dst;
    if (i < XN4) {
        src = x + 4 * i;
        dst = xt + 4 * i;
    } else {
        size_t wi = i - XN4;
        int w = (int)(wi / WN4);
        size_t off = (wi % WN4) * 4;
        const float* ws[4] = {Wq, Wk, Wv, Wp};
        src = ws[w] + off;
        dst = wt + (size_t)w * WELEM + off;
    }
    float4 v = *(const float4*)src;
    *(uint4*)dst = make_uint4(f2tf32(v.x), f2tf32(v.y), f2tf32(v.z), f2tf32(v.w));
}

// ---------------------------------------------------------------------------
// tf32 tensor-core GEMM (measured config: proj=231us): C = A @ W (+bias)
// 128x128 CTA tile, BK=16, 128 threads (4 warps 2x2), warp tile 64x64.
// 3-stage cp.async pipeline, one __syncthreads per K-iter.
// ---------------------------------------------------------------------------
#define BM 128
#define BN 128
#define BK 16
#define NT (D / BK)      // 48
#define ASTR 20
#define BSTR 132
#define A_WORDS (BM * ASTR)               // 2560
#define STAGE_WORDS (A_WORDS + BK * BSTR) // 4672

template <int OUTMODE>
__device__ __forceinline__ void gemm_body(const uint32_t* __restrict__ A,
                                          const uint32_t* __restrict__ W,
                                          void* __restrict__ Cout,
                                          const float* __restrict__ bias)
{
    __shared__ uint32_t smem[3 * STAGE_WORDS];

    const int tid = threadIdx.x;
    const int lane = tid & 31;
    const int warp = tid >> 5;
    const int g  = lane >> 2;
    const int tg = lane & 3;
    const int mb = (warp >> 1) * 64;
    const int nb = (warp & 1) * 64;
    const int m0 = blockIdx.y * BM;
    const int n0 = blockIdx.x * BN;

    const uint32_t smBase = (uint32_t)__cvta_generic_to_shared(smem);

    auto load_tiles = [&](int kt, int buf) {
        const uint32_t aS = smBase + (uint32_t)(buf * STAGE_WORDS) * 4;
        const uint32_t bS = aS + A_WORDS * 4;
#pragma unroll
        for (int i = 0; i < 4; ++i) {
            int c = tid + (i << 7);
            int row = c >> 2;
            int co = (c & 3) << 2;
            cp16(aS + (uint32_t)(row * ASTR + co) * 4,
                 A + (size_t)(m0 + row) * D + kt * BK + co);
        }
#pragma unroll
        for (int i = 0; i < 4; ++i) {
            int c = tid + (i << 7);
            int row = c >> 5;
            int col = (c & 31) << 2;
            cp16(bS + (uint32_t)(row * BSTR + col) * 4,
                 W + (size_t)(kt * BK + row) * D + n0 + col);
        }
    };

    float acc[4][8][4] = {};

    load_tiles(0, 0); CP_COMMIT();
    load_tiles(1, 1); CP_COMMIT();

    for (int kt = 0; kt < NT; ++kt) {
        const int buf = kt % 3;
        if (kt + 1 < NT) { CP_WAIT(1); } else { CP_WAIT(0); }
        __syncthreads();
        if (kt + 2 < NT) {
            load_tiles(kt + 2, (kt + 2) % 3);
            CP_COMMIT();
        }

        const uint32_t* as = smem + buf * STAGE_WORDS;
        const uint32_t* bs = as + A_WORDS;
#pragma unroll
        for (int kk = 0; kk < BK; kk += 8) {
            uint32_t af[4][4];
#pragma unroll
            for (int i = 0; i < 4; ++i) {
                const int r = (mb + i * 16 + g) * ASTR + kk + tg;
                af[i][0] = as[r];
                af[i][1] = as[r + 8 * ASTR];
                af[i][2] = as[r + 4];
                af[i][3] = as[r + 8 * ASTR + 4];
            }
#pragma unroll
            for (int j = 0; j < 8; ++j) {
                const uint32_t b0 = bs[(kk + tg) * BSTR + nb + j * 8 + g];
                const uint32_t b1 = bs[(kk + tg + 4) * BSTR + nb + j * 8 + g];
#pragma unroll
                for (int i = 0; i < 4; ++i)
                    mma_tf32(acc[i][j], af[i][0], af[i][1], af[i][2], af[i][3], b0, b1);
            }
        }
    }

    // Epilogue (validated c-frag map)
#pragma unroll
    for (int j = 0; j < 8; ++j) {
        const int cn = n0 + nb + j * 8 + 2 * tg;
        float b0 = 0.f, b1 = 0.f;
        if (OUTMODE == 1) { b0 = bias[cn]; b1 = bias[cn + 1]; }
#pragma unroll
        for (int i = 0; i < 4; ++i) {
            const int rm = m0 + mb + i * 16 + g;
            if (OUTMODE == 0) {
                uint32_t* C = (uint32_t*)Cout;
                *(uint2*)(C + (size_t)rm * D + cn) =
                    make_uint2(f2tf32(acc[i][j][0]), f2tf32(acc[i][j][1]));
                *(uint2*)(C + (size_t)(rm + 8) * D + cn) =
                    make_uint2(f2tf32(acc[i][j][2]), f2tf32(acc[i][j][3]));
            } else {
                float* C = (float*)Cout;
                *(float2*)(C + (size_t)rm * D + cn) =
                    make_float2(acc[i][j][0] + b0, acc[i][j][1] + b1);
                *(float2*)(C + (size_t)(rm + 8) * D + cn) =
                    make_float2(acc[i][j][2] + b0, acc[i][j][3] + b1);
            }
        }
    }
}

__global__ void __launch_bounds__(128) qkv_kernel()
{
    const uint32_t* W = g_wt + (size_t)blockIdx.z * WELEM;
    uint32_t* C = (blockIdx.z == 0) ? g_qt : (blockIdx.z == 1) ? g_kt : g_vt;
    gemm_body<0>(g_xt, W, C, nullptr);
}

__global__ void __launch_bounds__(128) proj_kernel(const float* __restrict__ bias,
                                                   float* __restrict__ out)
{
    gemm_body<1>(g_att, g_wt + 3 * (size_t)WELEM, out, bias);
}

// ---------------------------------------------------------------------------
// tf32 flash attention, 64-query tile, 128 threads (4 warps x 16 rows).
// Q frags hoisted to registers; Qt smem reused as P buffer (own-warp rows ->
// syncwarp only). 2 block syncs per key-tile. exp in log2 domain (ex2).
// Smem 52224B -> 4 CTAs/SM.
// ---------------------------------------------------------------------------
#define ATS 68
#define SM_QTP 0                      // phase 1: Qt [d][q]; phase 2: P [q][key]
#define SM_KS (64 * ATS)
#define SM_VS (2 * 64 * ATS)
#define SMEM_ATTN (3 * 64 * ATS * 4)  // 52224 B

__global__ void __launch_bounds__(128, 4) attn_kernel()
{
    extern __shared__ uint32_t sm[];
    uint32_t* QtP = sm + SM_QTP;
    uint32_t* Ks  = sm + SM_KS;
    uint32_t* Vs  = sm + SM_VS;

    const int qt = blockIdx.x, h = blockIdx.y, b = blockIdx.z;
    const int q0 = qt << 6;
    const int nq = min(64, LSEQ - q0);
    const int nk = (q0 < 128) ? 128 : LSEQ;
    const int tid = threadIdx.x;
    const int lane = tid & 31;
    const int warp = tid >> 5;      // 0..3
    const int g  = lane >> 2;
    const int tg = lane & 3;
    const int mrow = warp * 16;
    const size_t base = (size_t)b * LSEQ * D + (size_t)h * DH;

    // Load Q transposed: Qt[d][q]
#pragma unroll
    for (int it = 0; it < 8; ++it) {
        int idx = tid + (it << 7);
        int r = idx & 63;
        int c4 = (idx >> 6) << 2;
        uint4 v = make_uint4(0u, 0u, 0u, 0u);
        if (r < nq) v = *(const uint4*)(g_qt + base + (size_t)(q0 + r) * D + c4);
        QtP[(c4 + 0) * ATS + r] = v.x;
        QtP[(c4 + 1) * ATS + r] = v.y;
        QtP[(c4 + 2) * ATS + r] = v.z;
        QtP[(c4 + 3) * ATS + r] = v.w;
    }
    __syncthreads();

    // Hoist Q fragments into registers (Qt smem becomes the P buffer after this)
    uint32_t qf[8][4];
#pragma unroll
    for (int k8 = 0; k8 < 8; ++k8) {
        const int kk = k8 << 3;
        qf[k8][0] = QtP[(kk + tg) * ATS + mrow + g];
        qf[k8][1] = QtP[(kk + tg) * ATS + mrow + g + 8];
        qf[k8][2] = QtP[(kk + tg + 4) * ATS + mrow + g];
        qf[k8][3] = QtP[(kk + tg + 4) * ATS + mrow + g + 8];
    }

    float o[8][4] = {};
    float row_max[2] = {-1e30f, -1e30f};
    float row_sum[2] = {0.f, 0.f};

    for (int kt0 = 0; kt0 < nk; kt0 += 64) {
        const int nkv = min(64, nk - kt0);
        // Protects: Ks/Vs reuse vs prior-iter S/PV reads; and (iter 0) the
        // qf extraction above vs P writes below.
        __syncthreads();

        // Load K transposed + V row-major (zero-padded)
#pragma unroll
        for (int it = 0; it < 8; ++it) {
            int idx = tid + (it << 7);
            int r = idx & 63;
            int c4 = (idx >> 6) << 2;
            uint4 kv = make_uint4(0u, 0u, 0u, 0u);
            if (r < nkv) kv = *(const uint4*)(g_kt + base + (size_t)(kt0 + r) * D + c4);
            Ks[(c4 + 0) * ATS + r] = kv.x;
            Ks[(c4 + 1) * ATS + r] = kv.y;
            Ks[(c4 + 2) * ATS + r] = kv.z;
            Ks[(c4 + 3) * ATS + r] = kv.w;
            int r2 = idx >> 4;
            int c2 = (idx & 15) << 2;
            uint4 vv = make_uint4(0u, 0u, 0u, 0u);
            if (r2 < nkv) vv = *(const uint4*)(g_vt + base + (size_t)(kt0 + r2) * D + c2);
            *(uint4*)&Vs[r2 * ATS + c2] = vv;
        }
        __syncthreads();

        // S = Q K^T : warp rows [mrow, mrow+16) x 64 keys (log2-domain scores)
        float s[8][4] = {};
#pragma unroll
        for (int k8 = 0; k8 < 8; ++k8) {
            const int kk = k8 << 3;
#pragma unroll
            for (int j = 0; j < 8; ++j) {
                uint32_t b0 = Ks[(kk + tg) * ATS + j * 8 + g];
                uint32_t b1 = Ks[(kk + tg + 4) * ATS + j * 8 + g];
                mma_tf32(s[j], qf[k8][0], qf[k8][1], qf[k8][2], qf[k8][3], b0, b1);
            }
        }

        // scale (log2 domain); mask only on the partial last tile
        if (kt0 + 64 > nk) {
#pragma unroll
            for (int j = 0; j < 8; ++j) {
                const int col = kt0 + j * 8 + 2 * tg;
#pragma unroll
                for (int c = 0; c < 4; ++c) {
                    float sv = s[j][c] * SCALE2;
                    if (col + (c & 1) >= nk) sv = -1e30f;
                    s[j][c] = sv;
                }
            }
        } else {
#pragma unroll
            for (int j = 0; j < 8; ++j)
#pragma unroll
                for (int c = 0; c < 4; ++c) s[j][c] *= SCALE2;
        }

        // warp-local online softmax (log2 domain)
        float m0v = -1e30f, m1v = -1e30f;
#pragma unroll
        for (int j = 0; j < 8; ++j) {
            m0v = fmaxf(m0v, fmaxf(s[j][0], s[j][1]));
            m1v = fmaxf(m1v, fmaxf(s[j][2], s[j][3]));
        }
        m0v = fmaxf(m0v, __shfl_xor_sync(0xffffffffu, m0v, 1));
        m0v = fmaxf(m0v, __shfl_xor_sync(0xffffffffu, m0v, 2));
        m1v = fmaxf(m1v, __shfl_xor_sync(0xffffffffu, m1v, 1));
        m1v = fmaxf(m1v, __shfl_xor_sync(0xffffffffu, m1v, 2));

        float nm0 = fmaxf(row_max[0], m0v);
        float nm1 = fmaxf(row_max[1], m1v);
        float corr0 = ex2f(row_max[0] - nm0);
        float corr1 = ex2f(row_max[1] - nm1);
        row_max[0] = nm0; row_max[1] = nm1;
        row_sum[0] *= corr0; row_sum[1] *= corr1;
#pragma unroll
        for (int j = 0; j < 8; ++j) {
            o[j][0] *= corr0; o[j][1] *= corr0;
            o[j][2] *= corr1; o[j][3] *= corr1;
        }

        float ps0 = 0.f, ps1 = 0.f;
#pragma unroll
        for (int j = 0; j < 8; ++j) {
            const int col = j * 8 + 2 * tg;
            float p0 = ex2f(s[j][0] - nm0);
            float p1 = ex2f(s[j][1] - nm0);
            float p2 = ex2f(s[j][2] - nm1);
            float p3 = ex2f(s[j][3] - nm1);
            ps0 += p0 + p1; ps1 += p2 + p3;
            *(uint2*)&QtP[(mrow + g) * ATS + col] =
                make_uint2(f2tf32(p0), f2tf32(p1));
            *(uint2*)&QtP[(mrow + g + 8) * ATS + col] =
                make_uint2(f2tf32(p2), f2tf32(p3));
        }
        ps0 += __shfl_xor_sync(0xffffffffu, ps0, 1);
        ps0 += __shfl_xor_sync(0xffffffffu, ps0, 2);
        ps1 += __shfl_xor_sync(0xffffffffu, ps1, 1);
        ps1 += __shfl_xor_sync(0xffffffffu, ps1, 2);
        row_sum[0] += ps0; row_sum[1] += ps1;
        __syncwarp();   // own-warp P rows visible

        // O += P @ V (warp reads only its own P rows)
#pragma unroll
        for (int kk = 0; kk < 64; kk += 8) {
            uint32_t a0 = QtP[(mrow + g) * ATS + kk + tg];
            uint32_t a1 = QtP[(mrow + g + 8) * ATS + kk + tg];
            uint32_t a2 = QtP[(mrow + g) * ATS + kk + tg + 4];
            uint32_t a3 = QtP[(mrow + g + 8) * ATS + kk + tg + 4];
#pragma unroll
            for (int j = 0; j < 8; ++j) {
                uint32_t b0 = Vs[(kk + tg) * ATS + j * 8 + g];
                uint32_t b1 = Vs[(kk + tg + 4) * ATS + j * 8 + g];
                mma_tf32(o[j], a0, a1, a2, a3, b0, b1);
            }
        }
    }

    const int r0 = mrow + g, r1 = r0 + 8;
    const float inv0 = 1.f / row_sum[0];
    const float inv1 = 1.f / row_sum[1];
#pragma unroll
    for (int j = 0; j < 8; ++j) {
        const int cn = j * 8 + 2 * tg;
        if (r0 < nq)
            *(uint2*)(g_att + base + (size_t)(q0 + r0) * D + cn) =
                make_uint2(f2tf32(o[j][0] * inv0), f2tf32(o[j][1] * inv0));
        if (r1 < nq)
            *(uint2*)(g_att + base + (size_t)(q0 + r1) * D + cn) =
                make_uint2(f2tf32(o[j][2] * inv1), f2tf32(o[j][3] * inv1));
    }
}

// ---------------------------------------------------------------------------
extern "C" void kernel_launch(void* const* d_in, const int* in_sizes, int n_in,
                              void* d_out, int out_size)
{
    const float* x   = (const float*)d_in[0];
    const float* Wq  = (const float*)d_in[1];
    const float* Wk  = (const float*)d_in[2];
    const float* Wv  = (const float*)d_in[3];
    const float* Wp  = (const float*)d_in[4];
    const float* bp  = (const float*)d_in[5];
    float* out = (float*)d_out;

    cudaFuncSetAttribute(attn_kernel,
                         cudaFuncAttributeMaxDynamicSharedMemorySize, SMEM_ATTN);

    uint32_t* g_xt_p;  cudaGetSymbolAddress((void**)&g_xt_p, g_xt);
    uint32_t* g_wt_p;  cudaGetSymbolAddress((void**)&g_wt_p, g_wt);

    const int cvt_blocks = (int)((TOTN4 + 255) / 256);
    cvt_all_kernel<<<cvt_blocks, 256>>>(x, Wq, Wk, Wv, Wp, g_xt_p, g_wt_p);

    dim3 gq(D / BN, MTOT / BM, 3);           // (6, 264, 3)
    qkv_kernel<<<gq, 128>>>();

    dim3 ga((LSEQ + 63) / 64, NHEADS, BSZ);  // (9, 12, 64)
    attn_kernel<<<ga, 128, SMEM_ATTN>>>();

    dim3 gp(D / BN, MTOT / BM, 1);           // (6, 264)
    proj_kernel<<<gp, 128>>>(bp, out);
}

// round 12
// speedup vs baseline: 2.0142x; 1.7522x over previous
#include <cuda_runtime.h>
#include <cuda_fp16.h>
#include <cstdint>

#define D      768
#define DW     384                    // half2 words per row
#define LSEQ   528
#define BSZ    64
#define NHEADS 12
#define DH     64
#define MTOT   (BSZ * LSEQ)           // 33792
#define SCALE2 0.052058773f           // 768^-0.5 * log2(e)
#define WELEM  (D * D)

// Scratch (allocation-free rule). half2 packed as uint32.
__device__ uint32_t g_xh[(size_t)MTOT * DW];
__device__ uint32_t g_qh[(size_t)MTOT * DW];
__device__ uint32_t g_kh[(size_t)MTOT * DW];
__device__ uint32_t g_ah[(size_t)MTOT * DW];                  // attention out
__device__ __half   g_vth[(size_t)BSZ * NHEADS * DH * LSEQ];  // V^T per head
__device__ uint32_t g_wth[2 * (size_t)WELEM];                 // 4 x W^T halves

__device__ __forceinline__ uint32_t pack_h2(float lo, float hi) {
    __half2 h = __halves2half2(__float2half_rn(lo), __float2half_rn(hi));
    return *(uint32_t*)&h;
}

__device__ __forceinline__ float ex2f(float x) {
    float y;
    asm("ex2.approx.f32 %0, %1;" : "=f"(y) : "f"(x));
    return y;
}

__device__ __forceinline__ void mma_f16(float c[4], uint32_t a0, uint32_t a1,
                                        uint32_t a2, uint32_t a3,
                                        uint32_t b0, uint32_t b1) {
    asm volatile(
        "mma.sync.aligned.m16n8k16.row.col.f32.f16.f16.f32 "
        "{%0,%1,%2,%3}, {%4,%5,%6,%7}, {%8,%9}, {%0,%1,%2,%3};"
        : "+f"(c[0]), "+f"(c[1]), "+f"(c[2]), "+f"(c[3])
        : "r"(a0), "r"(a1), "r"(a2), "r"(a3), "r"(b0), "r"(b1));
}

__device__ __forceinline__ void cp16(uint32_t smem_dst, const void* gsrc) {
    asm volatile("cp.async.cg.shared.global [%0], [%1], 16;\n"
                 :: "r"(smem_dst), "l"(gsrc));
}
#define CP_COMMIT() asm volatile("cp.async.commit_group;\n" ::: "memory")
#define CP_WAIT(N)  asm volatile("cp.async.wait_group %0;\n" :: "n"(N) : "memory")

// ---------------------------------------------------------------------------
// fp32 -> fp16 converts
// ---------------------------------------------------------------------------
#define XN8 ((MTOT * (size_t)D) / 8)    // 3244032

__global__ void cvt_x_kernel(const float* __restrict__ x, uint32_t* __restrict__ xh)
{
    size_t i = (size_t)blockIdx.x * blockDim.x + threadIdx.x;
    if (i >= XN8) return;
    float4 a = *(const float4*)(x + 8 * i);
    float4 b = *(const float4*)(x + 8 * i + 4);
    uint4 u = make_uint4(pack_h2(a.x, a.y), pack_h2(a.z, a.w),
                         pack_h2(b.x, b.y), pack_h2(b.z, b.w));
    *(uint4*)(xh + 4 * i) = u;
}

// W [k][n] -> W^T [n][k] halves (32x32 tiled transpose)
__global__ void cvt_w_kernel(const float* __restrict__ Wq, const float* __restrict__ Wk,
                             const float* __restrict__ Wv, const float* __restrict__ Wp,
                             uint32_t* __restrict__ wt)
{
    __shared__ float t[32][33];
    const float* srcs[4] = {Wq, Wk, Wv, Wp};
    const float* S = srcs[blockIdx.z];
    __half* Dst = (__half*)(wt) + (size_t)blockIdx.z * WELEM;
    const int n0 = blockIdx.x * 32;
    const int k0 = blockIdx.y * 32;
    const int tx = threadIdx.x, ty = threadIdx.y;
#pragma unroll
    for (int i = 0; i < 4; ++i)
        t[ty + i * 8][tx] = S[(size_t)(k0 + ty + i * 8) * D + n0 + tx];
    __syncthreads();
#pragma unroll
    for (int i = 0; i < 4; ++i)
        Dst[(size_t)(n0 + ty + i * 8) * D + k0 + tx] = __float2half_rn(t[tx][ty + i * 8]);
}

// ---------------------------------------------------------------------------
// fp16 tensor-core GEMM: C[M,768] = A[M,768] @ W[768,768]
// A, W^T as half2 words, both [row][kpair] k-contiguous.
// 128x128 tile, BK=32 halves (16 words), 128 threads, warp tile 64x64.
// 3-stage cp.async pipeline.
// MODE 0: half2 out.  MODE 1: fp32 + bias.  MODE 2: V^T scatter (halves).
// ---------------------------------------------------------------------------
#define BKW 16
#define NT  24
#define ASTR 20
#define TILE_W (128 * ASTR)           // 2560 words
#define STG_W  (2 * TILE_W)           // 5120 words
#define GSMEM  (3 * STG_W * 4)        // 61440 B

__device__ __forceinline__ void gemm_body(const uint32_t* __restrict__ A,
                                          const uint32_t* __restrict__ W,
                                          void* __restrict__ Cout,
                                          const float* __restrict__ bias,
                                          int mode)
{
    extern __shared__ uint32_t gsm[];

    const int tid = threadIdx.x;
    const int lane = tid & 31;
    const int warp = tid >> 5;
    const int g  = lane >> 2;
    const int tg = lane & 3;
    const int mb = (warp >> 1) * 64;
    const int nb = (warp & 1) * 64;
    const int m0 = blockIdx.y * 128;
    const int n0 = blockIdx.x * 128;

    const uint32_t smBase = (uint32_t)__cvta_generic_to_shared(gsm);

    auto load_tiles = [&](int kt, int buf) {
        const uint32_t aS = smBase + (uint32_t)(buf * STG_W) * 4;
        const uint32_t bS = aS + TILE_W * 4;
#pragma unroll
        for (int i = 0; i < 4; ++i) {
            int c = tid + (i << 7);          // 0..511
            int row = c >> 2;
            int cw = (c & 3) << 2;           // word offset 0,4,8,12
            cp16(aS + (uint32_t)(row * ASTR + cw) * 4,
                 A + (size_t)(m0 + row) * DW + kt * BKW + cw);
        }
#pragma unroll
        for (int i = 0; i < 4; ++i) {
            int c = tid + (i << 7);
            int row = c >> 2;
            int cw = (c & 3) << 2;
            cp16(bS + (uint32_t)(row * ASTR + cw) * 4,
                 W + (size_t)(n0 + row) * DW + kt * BKW + cw);
        }
    };

    float acc[4][8][4] = {};

    load_tiles(0, 0); CP_COMMIT();
    load_tiles(1, 1); CP_COMMIT();

    for (int kt = 0; kt < NT; ++kt) {
        const int buf = kt % 3;
        if (kt + 1 < NT) { CP_WAIT(1); } else { CP_WAIT(0); }
        __syncthreads();
        if (kt + 2 < NT) {
            load_tiles(kt + 2, (kt + 2) % 3);
            CP_COMMIT();
        }

        const uint32_t* as = gsm + buf * STG_W;
        const uint32_t* bs = as + TILE_W;
#pragma unroll
        for (int kk = 0; kk < BKW; kk += 8) {
            uint32_t af[4][4];
#pragma unroll
            for (int i = 0; i < 4; ++i) {
                const int r = (mb + i * 16 + g) * ASTR + kk + tg;
                af[i][0] = as[r];
                af[i][1] = as[r + 8 * ASTR];
                af[i][2] = as[r + 4];
                af[i][3] = as[r + 8 * ASTR + 4];
            }
#pragma unroll
            for (int j = 0; j < 8; ++j) {
                const int br = (nb + j * 8 + g) * ASTR + kk + tg;
                const uint32_t b0 = bs[br];
                const uint32_t b1 = bs[br + 4];
#pragma unroll
                for (int i = 0; i < 4; ++i)
                    mma_f16(acc[i][j], af[i][0], af[i][1], af[i][2], af[i][3], b0, b1);
            }
        }
    }

    // Epilogue (c-frag map: c0,c1 = row g cols 2tg,2tg+1; c2,c3 = row g+8)
#pragma unroll
    for (int j = 0; j < 8; ++j) {
        const int cn = n0 + nb + j * 8 + 2 * tg;
#pragma unroll
        for (int i = 0; i < 4; ++i) {
            const int rm = m0 + mb + i * 16 + g;
            if (mode == 0) {
                uint32_t* C = (uint32_t*)Cout;
                const int cw = cn >> 1;
                C[(size_t)rm * DW + cw]       = pack_h2(acc[i][j][0], acc[i][j][1]);
                C[(size_t)(rm + 8) * DW + cw] = pack_h2(acc[i][j][2], acc[i][j][3]);
            } else if (mode == 1) {
                float* C = (float*)Cout;
                const float b0 = bias[cn], b1 = bias[cn + 1];
                *(float2*)(C + (size_t)rm * D + cn) =
                    make_float2(acc[i][j][0] + b0, acc[i][j][1] + b1);
                *(float2*)(C + (size_t)(rm + 8) * D + cn) =
                    make_float2(acc[i][j][2] + b0, acc[i][j][3] + b1);
            } else {
                // V^T scatter: g_vth[((b*12 + h)*64 + dh)*528 + pos]
                __half* Vt = (__half*)Cout;
                const int h = cn >> 6, dh = cn & 63;
                int b0i = rm / LSEQ, p0 = rm - b0i * LSEQ;
                int b1i = (rm + 8) / LSEQ, p1 = (rm + 8) - b1i * LSEQ;
                size_t base0 = (((size_t)b0i * NHEADS + h) * DH + dh) * LSEQ + p0;
                size_t base1 = (((size_t)b1i * NHEADS + h) * DH + dh) * LSEQ + p1;
                Vt[base0]        = __float2half_rn(acc[i][j][0]);
                Vt[base0 + LSEQ] = __float2half_rn(acc[i][j][1]);
                Vt[base1]        = __float2half_rn(acc[i][j][2]);
                Vt[base1 + LSEQ] = __float2half_rn(acc[i][j][3]);
            }
        }
    }
}

__global__ void __launch_bounds__(128) qkv_kernel()
{
    const uint32_t* W = g_wth + (size_t)blockIdx.z * (WELEM / 2);
    if (blockIdx.z == 0)      gemm_body(g_xh, W, g_qh,  nullptr, 0);
    else if (blockIdx.z == 1) gemm_body(g_xh, W, g_kh,  nullptr, 0);
    else                      gemm_body(g_xh, W, g_vth, nullptr, 2);
}

__global__ void __launch_bounds__(128) proj_kernel(const float* __restrict__ bias,
                                                   float* __restrict__ out)
{
    gemm_body(g_ah, g_wth + 3 * (size_t)(WELEM / 2), out, bias, 1);
}

// ---------------------------------------------------------------------------
// fp16 flash attention, 64-query tile, 128 threads (4 warps x 16 rows).
// All operands natural k-contiguous half2: Qs[q][dp], Ks[key][dp],
// Vs[dh][kp] (from pre-transposed g_vth), Ps[q][kp] (aliases Qs after hoist).
// All strides 40 words -> fragment banks g*8+tg, conflict-free.
// ---------------------------------------------------------------------------
#define ATS 40
#define SMA_Q 0                       // Qs then Ps
#define SMA_K (64 * ATS)
#define SMA_V (2 * 64 * ATS)

__global__ void __launch_bounds__(128, 4) attn_kernel()
{
    __shared__ uint32_t sm[3 * 64 * ATS];   // 30720 B
    uint32_t* QsPs = sm + SMA_Q;
    uint32_t* Ks   = sm + SMA_K;
    uint32_t* Vs   = sm + SMA_V;

    const int qt = blockIdx.x, h = blockIdx.y, b = blockIdx.z;
    const int q0 = qt << 6;
    const int nq = min(64, LSEQ - q0);
    const int nk = (q0 < 128) ? 128 : LSEQ;
    const int tid = threadIdx.x;
    const int lane = tid & 31;
    const int warp = tid >> 5;
    const int g  = lane >> 2;
    const int tg = lane & 3;
    const int mrow = warp * 16;
    const size_t qbase = ((size_t)b * LSEQ) * DW + (size_t)h * (DH / 2);
    const size_t vbase = (((size_t)b * NHEADS + h) * DH) * LSEQ;

    // Fill Qs[q][dp] (row = 32 words = 8 chunks)
#pragma unroll
    for (int it = 0; it < 4; ++it) {
        int c = tid + (it << 7);
        int r = c >> 3;
        int ch = c & 7;
        uint4 v = make_uint4(0u, 0u, 0u, 0u);
        if (r < nq) v = *(const uint4*)(g_qh + qbase + (size_t)(q0 + r) * DW + ch * 4);
        *(uint4*)&QsPs[r * ATS + ch * 4] = v;
    }
    __syncthreads();

    // Hoist Q fragments (4 ksteps of 8 dpairs); Qs becomes the P buffer after.
    uint32_t qf[4][4];
#pragma unroll
    for (int s4 = 0; s4 < 4; ++s4) {
        const int kk = s4 << 3;
        qf[s4][0] = QsPs[(mrow + g) * ATS + kk + tg];
        qf[s4][1] = QsPs[(mrow + g + 8) * ATS + kk + tg];
        qf[s4][2] = QsPs[(mrow + g) * ATS + kk + tg + 4];
        qf[s4][3] = QsPs[(mrow + g + 8) * ATS + kk + tg + 4];
    }

    float o[8][4] = {};
    float row_max[2] = {-1e30f, -1e30f};
    float row_sum[2] = {0.f, 0.f};

    for (int kt0 = 0; kt0 < nk; kt0 += 64) {
        const int nkv = min(64, nk - kt0);
        // protects: qf hoist (iter0) vs P writes; prior-iter S/PV reads vs fills
        __syncthreads();

        // Fill Ks[key][dp] + Vs[dh][kp]
#pragma unroll
        for (int it = 0; it < 4; ++it) {
            int c = tid + (it << 7);
            int r = c >> 3;
            int ch = c & 7;
            uint4 kv = make_uint4(0u, 0u, 0u, 0u);
            if (r < nkv)
                kv = *(const uint4*)(g_kh + qbase + (size_t)(kt0 + r) * DW + ch * 4);
            *(uint4*)&Ks[r * ATS + ch * 4] = kv;
            uint4 vv = make_uint4(0u, 0u, 0u, 0u);
            if (kt0 + ch * 8 < nk)
                vv = *(const uint4*)((const __half*)g_vth + vbase +
                                     (size_t)r * LSEQ + kt0 + ch * 8);
            *(uint4*)&Vs[r * ATS + ch * 4] = vv;
        }
        __syncthreads();

        // S = Q K^T
        float s[8][4] = {};
#pragma unroll
        for (int s4 = 0; s4 < 4; ++s4) {
            const int kk = s4 << 3;
#pragma unroll
            for (int j = 0; j < 8; ++j) {
                const int br = (j * 8 + g) * ATS + kk + tg;
                mma_f16(s[j], qf[s4][0], qf[s4][1], qf[s4][2], qf[s4][3],
                        Ks[br], Ks[br + 4]);
            }
        }

        // scale (log2 domain); mask only partial last tile
        if (kt0 + 64 > nk) {
#pragma unroll
            for (int j = 0; j < 8; ++j) {
                const int col = kt0 + j * 8 + 2 * tg;
#pragma unroll
                for (int c = 0; c < 4; ++c) {
                    float sv = s[j][c] * SCALE2;
                    if (col + (c & 1) >= nk) sv = -1e30f;
                    s[j][c] = sv;
                }
            }
        } else {
#pragma unroll
            for (int j = 0; j < 8; ++j)
#pragma unroll
                for (int c = 0; c < 4; ++c) s[j][c] *= SCALE2;
        }

        // warp-local online softmax
        float m0v = -1e30f, m1v = -1e30f;
#pragma unroll
        for (int j = 0; j < 8; ++j) {
            m0v = fmaxf(m0v, fmaxf(s[j][0], s[j][1]));
            m1v = fmaxf(m1v, fmaxf(s[j][2], s[j][3]));
        }
        m0v = fmaxf(m0v, __shfl_xor_sync(0xffffffffu, m0v, 1));
        m0v = fmaxf(m0v, __shfl_xor_sync(0xffffffffu, m0v, 2));
        m1v = fmaxf(m1v, __shfl_xor_sync(0xffffffffu, m1v, 1));
        m1v = fmaxf(m1v, __shfl_xor_sync(0xffffffffu, m1v, 2));

        float nm0 = fmaxf(row_max[0], m0v);
        float nm1 = fmaxf(row_max[1], m1v);
        float corr0 = ex2f(row_max[0] - nm0);
        float corr1 = ex2f(row_max[1] - nm1);
        row_max[0] = nm0; row_max[1] = nm1;
        row_sum[0] *= corr0; row_sum[1] *= corr1;
#pragma unroll
        for (int j = 0; j < 8; ++j) {
            o[j][0] *= corr0; o[j][1] *= corr0;
            o[j][2] *= corr1; o[j][3] *= corr1;
        }

        float ps0 = 0.f, ps1 = 0.f;
#pragma unroll
        for (int j = 0; j < 8; ++j) {
            float p0 = ex2f(s[j][0] - nm0);
            float p1 = ex2f(s[j][1] - nm0);
            float p2 = ex2f(s[j][2] - nm1);
            float p3 = ex2f(s[j][3] - nm1);
            ps0 += p0 + p1; ps1 += p2 + p3;
            const int cw = j * 4 + tg;
            QsPs[(mrow + g) * ATS + cw]     = pack_h2(p0, p1);
            QsPs[(mrow + g + 8) * ATS + cw] = pack_h2(p2, p3);
        }
        ps0 += __shfl_xor_sync(0xffffffffu, ps0, 1);
        ps0 += __shfl_xor_sync(0xffffffffu, ps0, 2);
        ps1 += __shfl_xor_sync(0xffffffffu, ps1, 1);
        ps1 += __shfl_xor_sync(0xffffffffu, ps1, 2);
        row_sum[0] += ps0; row_sum[1] += ps1;
        __syncwarp();   // own-warp P rows visible

        // O += P @ V   (A = P[q][kp], B = Vs[dh][kp])
#pragma unroll
        for (int s4 = 0; s4 < 4; ++s4) {
            const int kk = s4 << 3;
            uint32_t a0 = QsPs[(mrow + g) * ATS + kk + tg];
            uint32_t a1 = QsPs[(mrow + g + 8) * ATS + kk + tg];
            uint32_t a2 = QsPs[(mrow + g) * ATS + kk + tg + 4];
            uint32_t a3 = QsPs[(mrow + g + 8) * ATS + kk + tg + 4];
#pragma unroll
            for (int j = 0; j < 8; ++j) {
                const int br = (j * 8 + g) * ATS + kk + tg;
                mma_f16(o[j], a0, a1, a2, a3, Vs[br], Vs[br + 4]);
            }
        }
    }

    const int r0 = mrow + g, r1 = r0 + 8;
    const float inv0 = 1.f / row_sum[0];
    const float inv1 = 1.f / row_sum[1];
#pragma unroll
    for (int j = 0; j < 8; ++j) {
        const int cw = (size_t)0 + h * (DH / 2) + j * 4 + tg;
        if (r0 < nq)
            g_ah[((size_t)b * LSEQ + q0 + r0) * DW + cw] =
                pack_h2(o[j][0] * inv0, o[j][1] * inv0);
        if (r1 < nq)
            g_ah[((size_t)b * LSEQ + q0 + r1) * DW + cw] =
                pack_h2(o[j][2] * inv1, o[j][3] * inv1);
    }
}

// ---------------------------------------------------------------------------
extern "C" void kernel_launch(void* const* d_in, const int* in_sizes, int n_in,
                              void* d_out, int out_size)
{
    const float* x   = (const float*)d_in[0];
    const float* Wq  = (const float*)d_in[1];
    const float* Wk  = (const float*)d_in[2];
    const float* Wv  = (const float*)d_in[3];
    const float* Wp  = (const float*)d_in[4];
    const float* bp  = (const float*)d_in[5];
    float* out = (float*)d_out;

    cudaFuncSetAttribute(qkv_kernel,
                         cudaFuncAttributeMaxDynamicSharedMemorySize, GSMEM);
    cudaFuncSetAttribute(proj_kernel,
                         cudaFuncAttributeMaxDynamicSharedMemorySize, GSMEM);

    uint32_t* g_xh_p;  cudaGetSymbolAddress((void**)&g_xh_p, g_xh);
    uint32_t* g_wt_p;  cudaGetSymbolAddress((void**)&g_wt_p, g_wth);

    cvt_x_kernel<<<(int)((XN8 + 255) / 256), 256>>>(x, g_xh_p);
    cvt_w_kernel<<<dim3(24, 24, 4), dim3(32, 8)>>>(Wq, Wk, Wv, Wp, g_wt_p);

    dim3 gq(D / 128, MTOT / 128, 3);          // (6, 264, 3)
    qkv_kernel<<<gq, 128, GSMEM>>>();

    dim3 ga((LSEQ + 63) / 64, NHEADS, BSZ);   // (9, 12, 64)
    attn_kernel<<<ga, 128>>>();

    dim3 gp(D / 128, MTOT / 128, 1);          // (6, 264)
    proj_kernel<<<gp, 128, GSMEM>>>(bp, out);
}

// round 13
// speedup vs baseline: 2.8242x; 1.4022x over previous
#include <cuda_runtime.h>
#include <cuda_fp16.h>
#include <cstdint>

#define D      768
#define DW     384                    // half2 words per row
#define LSEQ   528
#define BSZ    64
#define NHEADS 12
#define DH     64
#define MTOT   (BSZ * LSEQ)           // 33792
#define SCALE2 0.052058773f           // 768^-0.5 * log2(e)
#define WELEM  (D * D)

// Scratch (allocation-free rule). half2 packed as uint32.
__device__ uint32_t g_xh[(size_t)MTOT * DW];
__device__ uint32_t g_qh[(size_t)MTOT * DW];
__device__ uint32_t g_kh[(size_t)MTOT * DW];
__device__ uint32_t g_ah[(size_t)MTOT * DW];                  // attention out
__device__ __half   g_vth[(size_t)BSZ * NHEADS * DH * LSEQ];  // V^T per head
__device__ uint32_t g_wth[2 * (size_t)WELEM];                 // 4 x W^T halves

__device__ __forceinline__ uint32_t pack_h2(float lo, float hi) {
    __half2 h = __halves2half2(__float2half_rn(lo), __float2half_rn(hi));
    return *(uint32_t*)&h;
}

__device__ __forceinline__ float ex2f(float x) {
    float y;
    asm("ex2.approx.f32 %0, %1;" : "=f"(y) : "f"(x));
    return y;
}

__device__ __forceinline__ void mma_f16(float c[4], uint32_t a0, uint32_t a1,
                                        uint32_t a2, uint32_t a3,
                                        uint32_t b0, uint32_t b1) {
    asm volatile(
        "mma.sync.aligned.m16n8k16.row.col.f32.f16.f16.f32 "
        "{%0,%1,%2,%3}, {%4,%5,%6,%7}, {%8,%9}, {%0,%1,%2,%3};"
        : "+f"(c[0]), "+f"(c[1]), "+f"(c[2]), "+f"(c[3])
        : "r"(a0), "r"(a1), "r"(a2), "r"(a3), "r"(b0), "r"(b1));
}

__device__ __forceinline__ void ldsm4(uint32_t& r0, uint32_t& r1,
                                      uint32_t& r2, uint32_t& r3, uint32_t addr) {
    asm volatile("ldmatrix.sync.aligned.m8n8.x4.shared.b16 {%0,%1,%2,%3}, [%4];"
                 : "=r"(r0), "=r"(r1), "=r"(r2), "=r"(r3) : "r"(addr));
}

__device__ __forceinline__ void cp16(uint32_t smem_dst, const void* gsrc) {
    asm volatile("cp.async.cg.shared.global [%0], [%1], 16;\n"
                 :: "r"(smem_dst), "l"(gsrc));
}
__device__ __forceinline__ void cp16z(uint32_t smem_dst, const void* gsrc, bool p) {
    int sz = p ? 16 : 0;
    asm volatile("cp.async.cg.shared.global [%0], [%1], 16, %2;\n"
                 :: "r"(smem_dst), "l"(gsrc), "r"(sz));
}
#define CP_COMMIT() asm volatile("cp.async.commit_group;\n" ::: "memory")
#define CP_WAIT(N)  asm volatile("cp.async.wait_group %0;\n" :: "n"(N) : "memory")

// ---------------------------------------------------------------------------
// fp32 -> fp16 converts
// ---------------------------------------------------------------------------
#define XN8 ((MTOT * (size_t)D) / 8)    // 3244032

__global__ void cvt_x_kernel(const float* __restrict__ x, uint32_t* __restrict__ xh)
{
    size_t i = (size_t)blockIdx.x * blockDim.x + threadIdx.x;
    if (i >= XN8) return;
    float4 a = *(const float4*)(x + 8 * i);
    float4 b = *(const float4*)(x + 8 * i + 4);
    uint4 u = make_uint4(pack_h2(a.x, a.y), pack_h2(a.z, a.w),
                         pack_h2(b.x, b.y), pack_h2(b.z, b.w));
    *(uint4*)(xh + 4 * i) = u;
}

__global__ void cvt_w_kernel(const float* __restrict__ Wq, const float* __restrict__ Wk,
                             const float* __restrict__ Wv, const float* __restrict__ Wp,
                             uint32_t* __restrict__ wt)
{
    __shared__ float t[32][33];
    const float* srcs[4] = {Wq, Wk, Wv, Wp};
    const float* S = srcs[blockIdx.z];
    __half* Dst = (__half*)(wt) + (size_t)blockIdx.z * WELEM;
    const int n0 = blockIdx.x * 32;
    const int k0 = blockIdx.y * 32;
    const int tx = threadIdx.x, ty = threadIdx.y;
#pragma unroll
    for (int i = 0; i < 4; ++i)
        t[ty + i * 8][tx] = S[(size_t)(k0 + ty + i * 8) * D + n0 + tx];
    __syncthreads();
#pragma unroll
    for (int i = 0; i < 4; ++i)
        Dst[(size_t)(n0 + ty + i * 8) * D + k0 + tx] = __float2half_rn(t[tx][ty + i * 8]);
}

// ---------------------------------------------------------------------------
// fp16 tensor-core GEMM with ldmatrix fragment loads.
// 128x128 tile, BK=32 halves (16 words), 128 threads, warp tile 64x64.
// 3-stage cp.async pipeline.
// ---------------------------------------------------------------------------
#define BKW 16
#define NT  24
#define ASTR 20
#define TILE_W (128 * ASTR)           // 2560 words
#define STG_W  (2 * TILE_W)           // 5120 words
#define GSMEM  (3 * STG_W * 4)        // 61440 B

__device__ __forceinline__ void gemm_body(const uint32_t* __restrict__ A,
                                          const uint32_t* __restrict__ W,
                                          void* __restrict__ Cout,
                                          const float* __restrict__ bias,
                                          int mode)
{
    extern __shared__ uint32_t gsm[];

    const int tid = threadIdx.x;
    const int lane = tid & 31;
    const int warp = tid >> 5;
    const int g  = lane >> 2;
    const int tg = lane & 3;
    const int mb = (warp >> 1) * 64;
    const int nb = (warp & 1) * 64;
    const int m0 = blockIdx.y * 128;
    const int n0 = blockIdx.x * 128;

    const uint32_t smBase = (uint32_t)__cvta_generic_to_shared(gsm);

    // ldmatrix per-lane row/col offsets
    const int arow = (lane & 7) + 8 * ((lane >> 3) & 1);   // A: row-sel bit3
    const int acol = 4 * (lane >> 4);                      // A: col-sel bit4
    const int brow = (lane & 7) + 8 * (lane >> 4);         // B: row-sel bit4
    const int bcol = 4 * ((lane >> 3) & 1);                // B: col-sel bit3

    auto load_tiles = [&](int kt, int buf) {
        const uint32_t aS = smBase + (uint32_t)(buf * STG_W) * 4;
        const uint32_t bS = aS + TILE_W * 4;
#pragma unroll
        for (int i = 0; i < 4; ++i) {
            int c = tid + (i << 7);
            int row = c >> 2;
            int cw = (c & 3) << 2;
            cp16(aS + (uint32_t)(row * ASTR + cw) * 4,
                 A + (size_t)(m0 + row) * DW + kt * BKW + cw);
        }
#pragma unroll
        for (int i = 0; i < 4; ++i) {
            int c = tid + (i << 7);
            int row = c >> 2;
            int cw = (c & 3) << 2;
            cp16(bS + (uint32_t)(row * ASTR + cw) * 4,
                 W + (size_t)(n0 + row) * DW + kt * BKW + cw);
        }
    };

    float acc[4][8][4] = {};

    load_tiles(0, 0); CP_COMMIT();
    load_tiles(1, 1); CP_COMMIT();

    for (int kt = 0; kt < NT; ++kt) {
        const int buf = kt % 3;
        if (kt + 1 < NT) { CP_WAIT(1); } else { CP_WAIT(0); }
        __syncthreads();
        if (kt + 2 < NT) {
            load_tiles(kt + 2, (kt + 2) % 3);
            CP_COMMIT();
        }

        const uint32_t aS = smBase + (uint32_t)(buf * STG_W) * 4;
        const uint32_t bS = aS + TILE_W * 4;
#pragma unroll
        for (int kk = 0; kk < BKW; kk += 8) {
            uint32_t af[4][4];
#pragma unroll
            for (int i = 0; i < 4; ++i)
                ldsm4(af[i][0], af[i][1], af[i][2], af[i][3],
                      aS + (uint32_t)((mb + i * 16 + arow) * ASTR + kk + acol) * 4);
#pragma unroll
            for (int jp = 0; jp < 4; ++jp) {
                uint32_t b0, b1, b2, b3;
                ldsm4(b0, b1, b2, b3,
                      bS + (uint32_t)((nb + jp * 16 + brow) * ASTR + kk + bcol) * 4);
#pragma unroll
                for (int i = 0; i < 4; ++i) {
                    mma_f16(acc[i][2 * jp],     af[i][0], af[i][1], af[i][2], af[i][3], b0, b1);
                    mma_f16(acc[i][2 * jp + 1], af[i][0], af[i][1], af[i][2], af[i][3], b2, b3);
                }
            }
        }
    }

    // Epilogue (c-frag map: c0,c1 = row g cols 2tg,2tg+1; c2,c3 = row g+8)
#pragma unroll
    for (int j = 0; j < 8; ++j) {
        const int cn = n0 + nb + j * 8 + 2 * tg;
#pragma unroll
        for (int i = 0; i < 4; ++i) {
            const int rm = m0 + mb + i * 16 + g;
            if (mode == 0) {
                uint32_t* C = (uint32_t*)Cout;
                const int cw = cn >> 1;
                C[(size_t)rm * DW + cw]       = pack_h2(acc[i][j][0], acc[i][j][1]);
                C[(size_t)(rm + 8) * DW + cw] = pack_h2(acc[i][j][2], acc[i][j][3]);
            } else if (mode == 1) {
                float* C = (float*)Cout;
                const float b0 = bias[cn], b1 = bias[cn + 1];
                *(float2*)(C + (size_t)rm * D + cn) =
                    make_float2(acc[i][j][0] + b0, acc[i][j][1] + b1);
                *(float2*)(C + (size_t)(rm + 8) * D + cn) =
                    make_float2(acc[i][j][2] + b0, acc[i][j][3] + b1);
            } else {
                __half* Vt = (__half*)Cout;
                const int h = cn >> 6, dh = cn & 63;
                int b0i = rm / LSEQ, p0 = rm - b0i * LSEQ;
                int b1i = (rm + 8) / LSEQ, p1 = (rm + 8) - b1i * LSEQ;
                size_t base0 = (((size_t)b0i * NHEADS + h) * DH + dh) * LSEQ + p0;
                size_t base1 = (((size_t)b1i * NHEADS + h) * DH + dh) * LSEQ + p1;
                Vt[base0]        = __float2half_rn(acc[i][j][0]);
                Vt[base0 + LSEQ] = __float2half_rn(acc[i][j][1]);
                Vt[base1]        = __float2half_rn(acc[i][j][2]);
                Vt[base1 + LSEQ] = __float2half_rn(acc[i][j][3]);
            }
        }
    }
}

__global__ void __launch_bounds__(128) qkv_kernel()
{
    const uint32_t* W = g_wth + (size_t)blockIdx.z * (WELEM / 2);
    if (blockIdx.z == 0)      gemm_body(g_xh, W, g_qh,  nullptr, 0);
    else if (blockIdx.z == 1) gemm_body(g_xh, W, g_kh,  nullptr, 0);
    else                      gemm_body(g_xh, W, g_vth, nullptr, 2);
}

__global__ void __launch_bounds__(128) proj_kernel(const float* __restrict__ bias,
                                                   float* __restrict__ out)
{
    gemm_body(g_ah, g_wth + 3 * (size_t)(WELEM / 2), out, bias, 1);
}

// ---------------------------------------------------------------------------
// fp16 flash attention: 64-query tile, 128 threads (4 warps x 16 rows).
// Register P-passing (no P smem), ldmatrix K/V fragments, double-buffered
// cp.async K/V fills. Stride 36 words -> LDSM conflict-free.
// Smem: Qstage + 2 stages x (K + V) = 5 * 64*36 words = 46080 B.
// ---------------------------------------------------------------------------
#define ATS 36
#define TILEW (64 * ATS)              // 2304 words per tile

__global__ void __launch_bounds__(128, 4) attn_kernel()
{
    __shared__ uint32_t sm[5 * TILEW];

    const int qt = blockIdx.x, h = blockIdx.y, b = blockIdx.z;
    const int q0 = qt << 6;
    const int nq = min(64, LSEQ - q0);
    const int nk = (q0 < 128) ? 128 : LSEQ;
    const int NTile = (nk + 63) >> 6;
    const int tid = threadIdx.x;
    const int lane = tid & 31;
    const int warp = tid >> 5;
    const int g  = lane >> 2;
    const int tg = lane & 3;
    const int mrow = warp * 16;
    const size_t qbase = ((size_t)b * LSEQ) * DW + (size_t)h * (DH / 2);
    const size_t vbase = (((size_t)b * NHEADS + h) * DH) * LSEQ;
    const __half* vsrc = (const __half*)g_vth + vbase;

    const uint32_t smBase = (uint32_t)__cvta_generic_to_shared(sm);
    const uint32_t qSt = smBase;                       // Q stage
    // stage s: K at smBase + (1 + 2s)*TILEW*4, V at + (2 + 2s)*TILEW*4

    const int arow = (lane & 7) + 8 * ((lane >> 3) & 1);
    const int acol = 4 * (lane >> 4);
    const int brow = (lane & 7) + 8 * (lane >> 4);
    const int bcol = 4 * ((lane >> 3) & 1);

    auto fill = [&](int tt, int stg) {
        const int kt0 = tt << 6;
        const uint32_t kS = smBase + (uint32_t)((1 + 2 * stg) * TILEW) * 4;
        const uint32_t vS = kS + (uint32_t)TILEW * 4;
#pragma unroll
        for (int it = 0; it < 4; ++it) {
            int c = tid + (it << 7);
            int r = c >> 3;
            int ch = c & 7;
            bool kp = (kt0 + r) < nk;
            cp16z(kS + (uint32_t)(r * ATS + ch * 4) * 4,
                  g_kh + qbase + (size_t)(kt0 + (kp ? r : 0)) * DW + ch * 4, kp);
            bool vp = (kt0 + ch * 8) < nk;
            cp16z(vS + (uint32_t)(r * ATS + ch * 4) * 4,
                  vsrc + (size_t)r * LSEQ + (vp ? (kt0 + ch * 8) : 0), vp);
        }
        CP_COMMIT();
    };

    // Stage Q (+tile0) | tile1
    {
#pragma unroll
        for (int it = 0; it < 4; ++it) {
            int c = tid + (it << 7);
            int r = c >> 3;
            int ch = c & 7;
            bool qp = r < nq;
            cp16z(qSt + (uint32_t)(r * ATS + ch * 4) * 4,
                  g_qh + qbase + (size_t)(q0 + (qp ? r : 0)) * DW + ch * 4, qp);
        }
        const int kt0 = 0;
        const uint32_t kS = smBase + (uint32_t)(1 * TILEW) * 4;
        const uint32_t vS = kS + (uint32_t)TILEW * 4;
#pragma unroll
        for (int it = 0; it < 4; ++it) {
            int c = tid + (it << 7);
            int r = c >> 3;
            int ch = c & 7;
            cp16(kS + (uint32_t)(r * ATS + ch * 4) * 4,
                 g_kh + qbase + (size_t)(kt0 + r) * DW + ch * 4);
            cp16(vS + (uint32_t)(r * ATS + ch * 4) * 4,
                 vsrc + (size_t)r * LSEQ + kt0 + ch * 8);
        }
        CP_COMMIT();
    }
    fill(1, 1);                 // NTile >= 2 always (nk >= 128)
    CP_WAIT(1);
    __syncthreads();            // Q + tile0 resident

    // Hoist Q fragments via ldmatrix
    uint32_t qf[4][4];
#pragma unroll
    for (int t = 0; t < 4; ++t)
        ldsm4(qf[t][0], qf[t][1], qf[t][2], qf[t][3],
              qSt + (uint32_t)((mrow + arow) * ATS + t * 8 + acol) * 4);

    float o[8][4] = {};
    float row_max[2] = {-1e30f, -1e30f};
    float row_sum[2] = {0.f, 0.f};

    for (int t = 0; t < NTile; ++t) {
        const int kt0 = t << 6;
        const int stg = t & 1;
        const uint32_t kS = smBase + (uint32_t)((1 + 2 * stg) * TILEW) * 4;
        const uint32_t vS = kS + (uint32_t)TILEW * 4;

        // S = Q K^T
        float s[8][4] = {};
#pragma unroll
        for (int ks = 0; ks < 4; ++ks) {
#pragma unroll
            for (int jp = 0; jp < 4; ++jp) {
                uint32_t b0, b1, b2, b3;
                ldsm4(b0, b1, b2, b3,
                      kS + (uint32_t)((jp * 16 + brow) * ATS + ks * 8 + bcol) * 4);
                mma_f16(s[2 * jp],     qf[ks][0], qf[ks][1], qf[ks][2], qf[ks][3], b0, b1);
                mma_f16(s[2 * jp + 1], qf[ks][0], qf[ks][1], qf[ks][2], qf[ks][3], b2, b3);
            }
        }

        // scale (log2 domain); mask only on the partial last tile
        if (kt0 + 64 > nk) {
#pragma unroll
            for (int j = 0; j < 8; ++j) {
                const int col = kt0 + j * 8 + 2 * tg;
#pragma unroll
                for (int c = 0; c < 4; ++c) {
                    float sv = s[j][c] * SCALE2;
                    if (col + (c & 1) >= nk) sv = -1e30f;
                    s[j][c] = sv;
                }
            }
        } else {
#pragma unroll
            for (int j = 0; j < 8; ++j)
#pragma unroll
                for (int c = 0; c < 4; ++c) s[j][c] *= SCALE2;
        }

        // warp-local online softmax
        float m0v = -1e30f, m1v = -1e30f;
#pragma unroll
        for (int j = 0; j < 8; ++j) {
            m0v = fmaxf(m0v, fmaxf(s[j][0], s[j][1]));
            m1v = fmaxf(m1v, fmaxf(s[j][2], s[j][3]));
        }
        m0v = fmaxf(m0v, __shfl_xor_sync(0xffffffffu, m0v, 1));
        m0v = fmaxf(m0v, __shfl_xor_sync(0xffffffffu, m0v, 2));
        m1v = fmaxf(m1v, __shfl_xor_sync(0xffffffffu, m1v, 1));
        m1v = fmaxf(m1v, __shfl_xor_sync(0xffffffffu, m1v, 2));

        float nm0 = fmaxf(row_max[0], m0v);
        float nm1 = fmaxf(row_max[1], m1v);
        float corr0 = ex2f(row_max[0] - nm0);
        float corr1 = ex2f(row_max[1] - nm1);
        row_max[0] = nm0; row_max[1] = nm1;
        row_sum[0] *= corr0; row_sum[1] *= corr1;
#pragma unroll
        for (int j = 0; j < 8; ++j) {
            o[j][0] *= corr0; o[j][1] *= corr0;
            o[j][2] *= corr1; o[j][3] *= corr1;
        }

        // exp + pack P into A-fragments (register passing, no smem)
        uint32_t pa[8][2];
        float ps0 = 0.f, ps1 = 0.f;
#pragma unroll
        for (int j = 0; j < 8; ++j) {
            float p0 = ex2f(s[j][0] - nm0);
            float p1 = ex2f(s[j][1] - nm0);
            float p2 = ex2f(s[j][2] - nm1);
            float p3 = ex2f(s[j][3] - nm1);
            ps0 += p0 + p1; ps1 += p2 + p3;
            pa[j][0] = pack_h2(p0, p1);
            pa[j][1] = pack_h2(p2, p3);
        }
        ps0 += __shfl_xor_sync(0xffffffffu, ps0, 1);
        ps0 += __shfl_xor_sync(0xffffffffu, ps0, 2);
        ps1 += __shfl_xor_sync(0xffffffffu, ps1, 1);
        ps1 += __shfl_xor_sync(0xffffffffu, ps1, 2);
        row_sum[0] += ps0; row_sum[1] += ps1;

        // O += P @ V  (A from registers, B via ldmatrix from Vs[dh][kp])
#pragma unroll
        for (int ks = 0; ks < 4; ++ks) {
            const uint32_t a0 = pa[2 * ks][0], a1 = pa[2 * ks][1];
            const uint32_t a2 = pa[2 * ks + 1][0], a3 = pa[2 * ks + 1][1];
#pragma unroll
            for (int jp = 0; jp < 4; ++jp) {
                uint32_t b0, b1, b2, b3;
                ldsm4(b0, b1, b2, b3,
                      vS + (uint32_t)((jp * 16 + brow) * ATS + ks * 8 + bcol) * 4);
                mma_f16(o[2 * jp],     a0, a1, a2, a3, b0, b1);
                mma_f16(o[2 * jp + 1], a0, a1, a2, a3, b2, b3);
            }
        }

        // pipeline: wait next tile's fill, then prefetch t+2 into this stage
        if (t + 1 < NTile) {
            CP_WAIT(0);
            __syncthreads();
            if (t + 2 < NTile) fill(t + 2, stg);
        }
    }

    const int r0 = mrow + g, r1 = r0 + 8;
    const float inv0 = 1.f / row_sum[0];
    const float inv1 = 1.f / row_sum[1];
#pragma unroll
    for (int j = 0; j < 8; ++j) {
        const int cw = h * (DH / 2) + j * 4 + tg;
        if (r0 < nq)
            g_ah[((size_t)b * LSEQ + q0 + r0) * DW + cw] =
                pack_h2(o[j][0] * inv0, o[j][1] * inv0);
        if (r1 < nq)
            g_ah[((size_t)b * LSEQ + q0 + r1) * DW + cw] =
                pack_h2(o[j][2] * inv1, o[j][3] * inv1);
    }
}

// ---------------------------------------------------------------------------
extern "C" void kernel_launch(void* const* d_in, const int* in_sizes, int n_in,
                              void* d_out, int out_size)
{
    const float* x   = (const float*)d_in[0];
    const float* Wq  = (const float*)d_in[1];
    const float* Wk  = (const float*)d_in[2];
    const float* Wv  = (const float*)d_in[3];
    const float* Wp  = (const float*)d_in[4];
    const float* bp  = (const float*)d_in[5];
    float* out = (float*)d_out;

    cudaFuncSetAttribute(qkv_kernel,
                         cudaFuncAttributeMaxDynamicSharedMemorySize, GSMEM);
    cudaFuncSetAttribute(proj_kernel,
                         cudaFuncAttributeMaxDynamicSharedMemorySize, GSMEM);

    uint32_t* g_xh_p;  cudaGetSymbolAddress((void**)&g_xh_p, g_xh);
    uint32_t* g_wt_p;  cudaGetSymbolAddress((void**)&g_wt_p, g_wth);

    cvt_x_kernel<<<(int)((XN8 + 255) / 256), 256>>>(x, g_xh_p);
    cvt_w_kernel<<<dim3(24, 24, 4), dim3(32, 8)>>>(Wq, Wk, Wv, Wp, g_wt_p);

    dim3 gq(D / 128, MTOT / 128, 3);          // (6, 264, 3)
    qkv_kernel<<<gq, 128, GSMEM>>>();

    dim3 ga((LSEQ + 63) / 64, NHEADS, BSZ);   // (9, 12, 64)
    attn_kernel<<<ga, 128>>>();

    dim3 gp(D / 128, MTOT / 128, 1);          // (6, 264)
    proj_kernel<<<gp, 128, GSMEM>>>(bp, out);
}